// round 15
// baseline (speedup 1.0000x reference)
#include <cuda_runtime.h>
#include <cuda_fp16.h>
#include <cstdint>

typedef unsigned long long u64;
typedef unsigned int u32;

// ---------- helpers ----------
__device__ __forceinline__ u32 smem_u32(const void* p){
    u32 a; asm("{ .reg .u64 t; cvta.to.shared.u64 t, %1; cvt.u32.u64 %0, t; }" : "=r"(a) : "l"(p)); return a;
}
// pack f16(lo),f16(hi) -> u32 (lo in low 16 bits)
__device__ __forceinline__ u32 hp2(float lo, float hi){
    u32 r; asm("cvt.rn.f16x2.f32 %0, %1, %2;" : "=r"(r) : "f"(hi), "f"(lo)); return r;
}
__device__ __forceinline__ void mma16816(float* d, const u32* a, const u32* b){
    asm volatile("mma.sync.aligned.m16n8k16.row.col.f32.f16.f16.f32 "
        "{%0,%1,%2,%3}, {%4,%5,%6,%7}, {%8,%9}, {%0,%1,%2,%3};"
        : "+f"(d[0]),"+f"(d[1]),"+f"(d[2]),"+f"(d[3])
        : "r"(a[0]),"r"(a[1]),"r"(a[2]),"r"(a[3]), "r"(b[0]),"r"(b[1]));
}
__device__ __forceinline__ void ldm4(u32 addr, u32* r){
    asm volatile("ldmatrix.sync.aligned.m8n8.x4.shared.b16 {%0,%1,%2,%3}, [%4];"
        : "=r"(r[0]),"=r"(r[1]),"=r"(r[2]),"=r"(r[3]) : "r"(addr));
}
__device__ __forceinline__ void cpa16(u32 dst, const void* src){
    asm volatile("cp.async.cg.shared.global [%0], [%1], 16;" :: "r"(dst), "l"(src));
}
#define CPCOMMIT() asm volatile("cp.async.commit_group;" ::: "memory")
#define CPWAIT(n)  asm volatile("cp.async.wait_group %0;" :: "n"(n) : "memory")

// ---------- prepped weights: [512 rows][136] fp16 (rows 0-383 W_in, 384-511 W_out) ----------
__device__ __align__(16) __half g_w[512 * 136];

__global__ void prep_kernel(const float* __restrict__ W_in, const float* __restrict__ W_out){
    int idx = blockIdx.x * 256 + threadIdx.x;      // 65536
    int r = idx >> 7, c = idx & 127;
    float v = (r < 384) ? W_in[r * 128 + c] : W_out[(r - 384) * 128 + c];
    g_w[r * 136 + c] = __float2half(v);
}

// ---------- smem layout (32-bit word indices) ----------
#define OWS0  0          // 3 W stage buffers, 4352 words each
#define OWS1  4352
#define OWS2  8704
#define OKH   13056      // K fp16 [64 rows][68 words]
#define OVTH  17408      // V^T fp16 [128 d][36 words]
#define OCXH  22016      // ctx fp16 [64 rows][68 words]
#define OQA   13056      // attended fp32 [64][128] — overlaps K+V (dead after attention)
#define OPOOL 26368
#define OAW   26880
#define SMEM_FLOATS 26944
#define SMEM_BYTES  (SMEM_FLOATS * 4)   // 107,776 B -> 2 CTAs/SM
#define SCL 0.17677669529663687f        // 1/sqrt(32)

#define NT 256

__device__ __forceinline__ void issue_stage(int tid, int s, u32 bufw, u32 smb){
    const __half* sh = g_w + (size_t)s * 8704;
    for (int i = tid; i < 1088; i += NT){
        cpa16(smb + (bufw + (u32)i * 4) * 4, sh + i * 8);
    }
}

__global__ void __launch_bounds__(NT, 2)
feat_kernel(const float* __restrict__ xg_all,
            const float* __restrict__ b_in, const float* __restrict__ b_out,
            const float* __restrict__ W_pool, const float* __restrict__ b_pool,
            float* __restrict__ out)
{
    extern __shared__ float sm[];
    u32* smw = (u32*)sm;
    const u32 smb = smem_u32(sm);
    const int tid  = threadIdx.x;
    const int lane = tid & 31;
    const int warp = tid >> 5;        // 0..7
    const int q4   = lane >> 2;       // 0..7
    const int t4   = lane & 3;        // 0..3
    const int s16  = (warp & 3) * 16; // row stripe
    const int nh   = warp >> 2;       // 0..1 column half
    const int l8   = lane & 7;        // ldmatrix row-lane
    const int g8   = lane >> 3;       // ldmatrix matrix-group
    const int bm   = blockIdx.x;
    const float* xg = xg_all + (size_t)bm * (64 * 128);
    const u32 bufs[3] = {OWS0, OWS1, OWS2};

    // prefetch W stages 0,1
    issue_stage(tid, 0, OWS0, smb); CPCOMMIT();
    issue_stage(tid, 1, OWS1, smb); CPCOMMIT();

    // ---- A fragments from gmem x (fp16) ----
    u32 Ah[32];
    #pragma unroll
    for (int ks = 0; ks < 8; ++ks){
        #pragma unroll
        for (int qq = 0; qq < 4; ++qq){
            int rr = s16 + q4 + (qq & 1) * 8;
            int k  = ks * 16 + 2 * t4 + (qq >> 1) * 8;
            float2 v = *(const float2*)(xg + rr * 128 + k);
            Ah[4 * ks + qq] = hp2(v.x, v.y);
        }
    }

    u32 QAh[16];   // Q A-frags: 2 heads x 2 ksteps x 4 (register-resident)

    // ---------------- QKV, triple-buffered, ONE sync per stage ----------------
    for (int si = 0; si < 6; ++si){
        CPWAIT(1);
        __syncthreads();                             // stage si data visible; buf (si+2)%3 free
        issue_stage(tid, si + 2, bufs[(si + 2) % 3], smb); CPCOMMIT();
        const u32 bufw = bufs[si % 3];
        for (int j = 0; j < 4; ++j){
            float acc[4] = {0.f, 0.f, 0.f, 0.f};
            u32 baddr = smb + (bufw + (u32)(nh * 32 + 8 * j + l8) * 68) * 4 + g8 * 16;
            #pragma unroll
            for (int p = 0; p < 4; ++p){
                u32 Bh[4];
                ldm4(baddr + p * 64, Bh);
                mma16816(acc, &Ah[8*p],     &Bh[0]);
                mma16816(acc, &Ah[8*p + 4], &Bh[2]);
            }
            int e0 = si * 64 + nh * 32 + 8 * j + 2 * t4;
            int r0 = s16 + q4;
            float v0 = acc[0] + b_in[e0];
            float v1 = acc[1] + b_in[e0 + 1];
            float v2 = acc[2] + b_in[e0];
            float v3 = acc[3] + b_in[e0 + 1];
            if (si < 2){
                // Q (scaled) -> register A-frags (R9-validated mapping)
                v0 *= SCL; v1 *= SCL; v2 *= SCL; v3 *= SCL;
                int base = si * 8 + (j >> 1) * 4 + (j & 1) * 2;
                QAh[base]     = hp2(v0, v1);
                QAh[base + 1] = hp2(v2, v3);
            } else if (si < 4){
                // K row-major fp16
                int kw = (si - 2) * 32 + nh * 16 + 4 * j + t4;
                smw[OKH + r0 * 68 + kw]       = hp2(v0, v1);
                smw[OKH + (r0 + 8) * 68 + kw] = hp2(v2, v3);
            } else {
                // V^T fp16 (halfword stores)
                int d0 = (si - 4) * 64 + nh * 32 + 8 * j + 2 * t4;
                __half* vth = (__half*)&smw[OVTH];
                vth[d0 * 72 + r0]           = __float2half(v0);
                vth[(d0 + 1) * 72 + r0]     = __float2half(v1);
                vth[d0 * 72 + r0 + 8]       = __float2half(v2);
                vth[(d0 + 1) * 72 + r0 + 8] = __float2half(v3);
            }
        }
    }
    __syncthreads();   // K/V visible to all

    // ---------------- attention: mma, TWO heads per warp (h = nh + 2*hid) ----------------
    {
        const int r0 = s16 + q4;
        #pragma unroll
        for (int hid = 0; hid < 2; ++hid){
            const int h = nh + 2 * hid;
            float Sf[32];          // 8 nb x 4
            #pragma unroll
            for (int i = 0; i < 32; ++i) Sf[i] = 0.f;
            // S = Q.K^T  (Q from registers)
            #pragma unroll
            for (int nb = 0; nb < 8; ++nb){
                u32 kaddr = smb + (u32)(OKH + (8 * nb + l8) * 68 + h * 16) * 4 + g8 * 16;
                u32 Bh4[4];
                ldm4(kaddr, Bh4);
                mma16816(&Sf[nb*4], &QAh[hid*8],     &Bh4[0]);
                mma16816(&Sf[nb*4], &QAh[hid*8 + 4], &Bh4[2]);
            }
            // fragment softmax: rows r0 (idx 0,1) and r0+8 (idx 2,3)
            float mx0 = -3.4e38f, mx1 = -3.4e38f;
            #pragma unroll
            for (int nb = 0; nb < 8; ++nb){
                mx0 = fmaxf(mx0, fmaxf(Sf[nb*4],     Sf[nb*4 + 1]));
                mx1 = fmaxf(mx1, fmaxf(Sf[nb*4 + 2], Sf[nb*4 + 3]));
            }
            mx0 = fmaxf(mx0, __shfl_xor_sync(0xffffffffu, mx0, 1));
            mx0 = fmaxf(mx0, __shfl_xor_sync(0xffffffffu, mx0, 2));
            mx1 = fmaxf(mx1, __shfl_xor_sync(0xffffffffu, mx1, 1));
            mx1 = fmaxf(mx1, __shfl_xor_sync(0xffffffffu, mx1, 2));
            float sum0 = 0.f, sum1 = 0.f;
            #pragma unroll
            for (int nb = 0; nb < 8; ++nb){
                Sf[nb*4]     = __expf(Sf[nb*4]     - mx0);
                Sf[nb*4 + 1] = __expf(Sf[nb*4 + 1] - mx0);
                Sf[nb*4 + 2] = __expf(Sf[nb*4 + 2] - mx1);
                Sf[nb*4 + 3] = __expf(Sf[nb*4 + 3] - mx1);
                sum0 += Sf[nb*4] + Sf[nb*4 + 1];
                sum1 += Sf[nb*4 + 2] + Sf[nb*4 + 3];
            }
            sum0 += __shfl_xor_sync(0xffffffffu, sum0, 1);
            sum0 += __shfl_xor_sync(0xffffffffu, sum0, 2);
            sum1 += __shfl_xor_sync(0xffffffffu, sum1, 1);
            sum1 += __shfl_xor_sync(0xffffffffu, sum1, 2);
            float inv0 = 1.0f / sum0, inv1 = 1.0f / sum1;
            // P frags (fp16)
            u32 Pa[16];
            #pragma unroll
            for (int k2 = 0; k2 < 4; ++k2){
                Pa[k2*4]     = hp2(Sf[(2*k2)*4]     * inv0, Sf[(2*k2)*4 + 1] * inv0);
                Pa[k2*4 + 1] = hp2(Sf[(2*k2)*4 + 2] * inv1, Sf[(2*k2)*4 + 3] * inv1);
                Pa[k2*4 + 2] = hp2(Sf[(2*k2+1)*4]     * inv0, Sf[(2*k2+1)*4 + 1] * inv0);
                Pa[k2*4 + 3] = hp2(Sf[(2*k2+1)*4 + 2] * inv1, Sf[(2*k2+1)*4 + 3] * inv1);
            }
            // ctx = P.V
            #pragma unroll
            for (int nb2 = 0; nb2 < 4; ++nb2){
                float C[4] = {0.f,0.f,0.f,0.f};
                u32 vaddr = smb + (u32)(OVTH + (h * 32 + 8 * nb2 + l8) * 36) * 4 + g8 * 16;
                u32 Vh[8];
                ldm4(vaddr,      Vh);
                ldm4(vaddr + 64, Vh + 4);
                #pragma unroll
                for (int k2 = 0; k2 < 4; ++k2)
                    mma16816(C, &Pa[k2*4], &Vh[2*k2]);
                // ctx writeback as fp16 A-layout
                int w = h * 16 + 4 * nb2 + t4;
                smw[OCXH + r0 * 68 + w]       = hp2(C[0], C[1]);
                smw[OCXH + (r0 + 8) * 68 + w] = hp2(C[2], C[3]);
            }
        }
    }
    CPWAIT(0);
    __syncthreads();   // ctx visible; K/V dead -> QA region reusable; W_out bufs ready

    // ---------------- out-proj: ctx(fp16) @ W_out^T + b_out -> QA ----------------
    {
        #pragma unroll
        for (int ks = 0; ks < 8; ++ks){
            u32 aaddr = smb + (u32)(OCXH + (s16 + ((lane >> 3) & 1) * 8 + l8) * 68
                                    + 8 * ks + (lane >> 4) * 4) * 4;
            ldm4(aaddr, &Ah[ks*4]);
        }
        for (int si = 0; si < 2; ++si){
            const u32 bufw = bufs[si];     // stages 6,7 -> bufs 0,1
            for (int j = 0; j < 4; ++j){
                float acc[4] = {0.f, 0.f, 0.f, 0.f};
                u32 baddr = smb + (bufw + (u32)(nh * 32 + 8 * j + l8) * 68) * 4 + g8 * 16;
                #pragma unroll
                for (int p = 0; p < 4; ++p){
                    u32 Bh[4];
                    ldm4(baddr + p * 64, Bh);
                    mma16816(acc, &Ah[8*p],     &Bh[0]);
                    mma16816(acc, &Ah[8*p + 4], &Bh[2]);
                }
                int e0 = si * 64 + nh * 32 + 8 * j + 2 * t4;
                int r0 = s16 + q4;
                sm[OQA + r0 * 128 + e0]           = acc[0] + b_out[e0];
                sm[OQA + r0 * 128 + e0 + 1]       = acc[1] + b_out[e0 + 1];
                sm[OQA + (r0 + 8) * 128 + e0]     = acc[2] + b_out[e0];
                sm[OQA + (r0 + 8) * 128 + e0 + 1] = acc[3] + b_out[e0 + 1];
            }
        }
    }
    __syncthreads();

    // ---------------- pooling + projections ----------------
    #pragma unroll
    for (int i = 0; i < 8; ++i) {
        int l = warp * 8 + i;
        float p = 0.f;
        #pragma unroll
        for (int c = 0; c < 4; ++c) {
            int d = lane + 32 * c;
            p = fmaf(sm[OQA + l * 128 + d], xg[l * 128 + d], p);
        }
        #pragma unroll
        for (int o = 16; o > 0; o >>= 1) p += __shfl_xor_sync(0xffffffffu, p, o);
        if (lane == 0) sm[OAW + l] = p;
    }
    __syncthreads();
    if (warp == 0) {
        float va = sm[OAW + lane], vb = sm[OAW + lane + 32];
        float mx = fmaxf(va, vb);
        #pragma unroll
        for (int o = 16; o > 0; o >>= 1)
            mx = fmaxf(mx, __shfl_xor_sync(0xffffffffu, mx, o));
        float ea = __expf(va - mx), eb = __expf(vb - mx);
        float s = ea + eb;
        #pragma unroll
        for (int o = 16; o > 0; o >>= 1) s += __shfl_xor_sync(0xffffffffu, s, o);
        float inv = 1.0f / s;
        sm[OAW + lane]      = ea * inv;
        sm[OAW + lane + 32] = eb * inv;
    }
    __syncthreads();
    if (tid < 128) {
        int d = tid;
        float wacc = 0.f, s = 0.f, s2 = 0.f, mx = -3.4e38f;
        #pragma unroll 8
        for (int l = 0; l < 64; ++l) {
            float a = sm[OQA + l * 128 + d];
            wacc = fmaf(sm[OAW + l], a, wacc);
            s += a;
            s2 = fmaf(a, a, s2);
            mx = fmaxf(mx, a);
        }
        float mean = s * (1.0f / 64.0f);
        float var  = (s2 - s * mean) * (1.0f / 63.0f);
        sm[OPOOL + d]       = wacc;
        sm[OPOOL + 128 + d] = mx;
        sm[OPOOL + 256 + d] = mean;
        sm[OPOOL + 384 + d] = sqrtf(fmaxf(var, 0.0f));
    }
    __syncthreads();
    {
        int p  = warp >> 1;            // 0..3 pool slot
        int f0 = (warp & 1) * 8;       // 8 outputs per warp
        #pragma unroll
        for (int fi = 0; fi < 8; ++fi) {
            int o = p * 16 + f0 + fi;
            float acc = 0.f;
            #pragma unroll
            for (int c = 0; c < 4; ++c) {
                int d = lane + 32 * c;
                acc = fmaf(sm[OPOOL + p * 128 + d], W_pool[(size_t)o * 128 + d], acc);
            }
            #pragma unroll
            for (int off = 16; off > 0; off >>= 1)
                acc += __shfl_xor_sync(0xffffffffu, acc, off);
            if (lane == 0) out[(size_t)bm * 64 + o] = acc + b_pool[o];
        }
    }
}

extern "C" void kernel_launch(void* const* d_in, const int* in_sizes, int n_in,
                              void* d_out, int out_size)
{
    const float* x      = (const float*)d_in[0];
    const float* W_in   = (const float*)d_in[2];
    const float* b_in   = (const float*)d_in[3];
    const float* W_out  = (const float*)d_in[4];
    const float* b_out  = (const float*)d_in[5];
    const float* W_pool = (const float*)d_in[6];
    const float* b_pool = (const float*)d_in[7];
    float* out = (float*)d_out;

    int nmol = in_sizes[0] / (64 * 128);   // 8192

    prep_kernel<<<256, 256>>>(W_in, W_out);
    cudaFuncSetAttribute(feat_kernel,
                         cudaFuncAttributeMaxDynamicSharedMemorySize, SMEM_BYTES);
    feat_kernel<<<nmol, NT, SMEM_BYTES>>>(x, b_in, b_out,
                                          W_pool, b_pool, out);
}

// round 16
// speedup vs baseline: 1.0814x; 1.0814x over previous
#include <cuda_runtime.h>
#include <cuda_fp16.h>
#include <cstdint>

typedef unsigned long long u64;
typedef unsigned int u32;

// ---------- helpers ----------
__device__ __forceinline__ u32 smem_u32(const void* p){
    u32 a; asm("{ .reg .u64 t; cvta.to.shared.u64 t, %1; cvt.u32.u64 %0, t; }" : "=r"(a) : "l"(p)); return a;
}
// pack f16(lo),f16(hi) -> u32 (lo in low 16 bits)
__device__ __forceinline__ u32 hp2(float lo, float hi){
    u32 r; asm("cvt.rn.f16x2.f32 %0, %1, %2;" : "=r"(r) : "f"(hi), "f"(lo)); return r;
}
__device__ __forceinline__ void mma16816(float* d, const u32* a, const u32* b){
    asm volatile("mma.sync.aligned.m16n8k16.row.col.f32.f16.f16.f32 "
        "{%0,%1,%2,%3}, {%4,%5,%6,%7}, {%8,%9}, {%0,%1,%2,%3};"
        : "+f"(d[0]),"+f"(d[1]),"+f"(d[2]),"+f"(d[3])
        : "r"(a[0]),"r"(a[1]),"r"(a[2]),"r"(a[3]), "r"(b[0]),"r"(b[1]));
}
__device__ __forceinline__ void ldm4(u32 addr, u32* r){
    asm volatile("ldmatrix.sync.aligned.m8n8.x4.shared.b16 {%0,%1,%2,%3}, [%4];"
        : "=r"(r[0]),"=r"(r[1]),"=r"(r[2]),"=r"(r[3]) : "r"(addr));
}
__device__ __forceinline__ void cpa16(u32 dst, const void* src){
    asm volatile("cp.async.cg.shared.global [%0], [%1], 16;" :: "r"(dst), "l"(src));
}
#define CPCOMMIT() asm volatile("cp.async.commit_group;" ::: "memory")
#define CPWAIT(n)  asm volatile("cp.async.wait_group %0;" :: "n"(n) : "memory")

// ---------- prepped weights: [512 rows][136] fp16 (rows 0-383 W_in, 384-511 W_out) ----------
__device__ __align__(16) __half g_w[512 * 136];

__global__ void prep_kernel(const float* __restrict__ W_in, const float* __restrict__ W_out){
    int idx = blockIdx.x * 256 + threadIdx.x;      // 65536
    int r = idx >> 7, c = idx & 127;
    float v = (r < 384) ? W_in[r * 128 + c] : W_out[(r - 384) * 128 + c];
    g_w[r * 136 + c] = __float2half(v);
}

// ---------- smem layout (32-bit word indices) ----------
#define OWS0  0          // 3 W stage buffers, 4352 words each
#define OWS1  4352
#define OWS2  8704
#define OKH   13056      // K fp16 [64 rows][68 words]
#define OVTH  17408      // V^T fp16 [128 d][36 words]
#define OCXH  22016      // ctx fp16 [64 rows][68 words]
#define OQA   13056      // attended fp32 [64][128] — overlaps K+V (dead after attention)
#define OPOOL 26368
#define OAW   26880
#define SMEM_FLOATS 26944
#define SMEM_BYTES  (SMEM_FLOATS * 4)   // 107,776 B -> 2 CTAs/SM
#define SCL 0.17677669529663687f        // 1/sqrt(32)

#define NT 256

__device__ __forceinline__ void issue_stage(int tid, int s, u32 bufw, u32 smb){
    const __half* sh = g_w + (size_t)s * 8704;
    for (int i = tid; i < 1088; i += NT){
        cpa16(smb + (bufw + (u32)i * 4) * 4, sh + i * 8);
    }
}

__global__ void __launch_bounds__(NT, 2)
feat_kernel(const float* __restrict__ xg_all,
            const float* __restrict__ b_in, const float* __restrict__ b_out,
            const float* __restrict__ W_pool, const float* __restrict__ b_pool,
            float* __restrict__ out)
{
    extern __shared__ float sm[];
    u32* smw = (u32*)sm;
    const u32 smb = smem_u32(sm);
    const int tid  = threadIdx.x;
    const int lane = tid & 31;
    const int warp = tid >> 5;        // 0..7
    const int q4   = lane >> 2;       // 0..7
    const int t4   = lane & 3;        // 0..3
    const int s16  = (warp & 3) * 16; // row stripe
    const int nh   = warp >> 2;       // 0..1 column half
    const int l8   = lane & 7;        // ldmatrix row-lane
    const int g8   = lane >> 3;       // ldmatrix matrix-group
    const int bm   = blockIdx.x;
    const float* xg = xg_all + (size_t)bm * (64 * 128);
    const u32 bufs[3] = {OWS0, OWS1, OWS2};

    // prefetch W stages 0,1
    issue_stage(tid, 0, OWS0, smb); CPCOMMIT();
    issue_stage(tid, 1, OWS1, smb); CPCOMMIT();

    // ---- A fragments from gmem x (fp16) ----
    u32 Ah[32];
    #pragma unroll
    for (int ks = 0; ks < 8; ++ks){
        #pragma unroll
        for (int qq = 0; qq < 4; ++qq){
            int rr = s16 + q4 + (qq & 1) * 8;
            int k  = ks * 16 + 2 * t4 + (qq >> 1) * 8;
            float2 v = *(const float2*)(xg + rr * 128 + k);
            Ah[4 * ks + qq] = hp2(v.x, v.y);
        }
    }

    u32 QAh[16];   // Q A-frags: 2 heads x 2 ksteps x 4 (register-resident)

    // ---------------- QKV, triple-buffered, ONE sync per stage, issue at BOTTOM ----------------
    for (int si = 0; si < 6; ++si){
        CPWAIT(1);
        __syncthreads();                             // stage si data visible
        const u32 bufw = bufs[si % 3];
        for (int j = 0; j < 4; ++j){
            float acc[4] = {0.f, 0.f, 0.f, 0.f};
            u32 baddr = smb + (bufw + (u32)(nh * 32 + 8 * j + l8) * 68) * 4 + g8 * 16;
            #pragma unroll
            for (int p = 0; p < 4; ++p){
                u32 Bh[4];
                ldm4(baddr + p * 64, Bh);
                mma16816(acc, &Ah[8*p],     &Bh[0]);
                mma16816(acc, &Ah[8*p + 4], &Bh[2]);
            }
            int e0 = si * 64 + nh * 32 + 8 * j + 2 * t4;
            int r0 = s16 + q4;
            float v0 = acc[0] + b_in[e0];
            float v1 = acc[1] + b_in[e0 + 1];
            float v2 = acc[2] + b_in[e0];
            float v3 = acc[3] + b_in[e0 + 1];
            if (si < 2){
                // Q (scaled) -> register A-frags (R9-validated mapping)
                v0 *= SCL; v1 *= SCL; v2 *= SCL; v3 *= SCL;
                int base = si * 8 + (j >> 1) * 4 + (j & 1) * 2;
                QAh[base]     = hp2(v0, v1);
                QAh[base + 1] = hp2(v2, v3);
            } else if (si < 4){
                // K row-major fp16
                int kw = (si - 2) * 32 + nh * 16 + 4 * j + t4;
                smw[OKH + r0 * 68 + kw]       = hp2(v0, v1);
                smw[OKH + (r0 + 8) * 68 + kw] = hp2(v2, v3);
            } else {
                // V^T fp16 (halfword stores)
                int d0 = (si - 4) * 64 + nh * 32 + 8 * j + 2 * t4;
                __half* vth = (__half*)&smw[OVTH];
                vth[d0 * 72 + r0]           = __float2half(v0);
                vth[(d0 + 1) * 72 + r0]     = __float2half(v1);
                vth[d0 * 72 + r0 + 8]       = __float2half(v2);
                vth[(d0 + 1) * 72 + r0 + 8] = __float2half(v3);
            }
        }
        // issue stage si+2 into buf (si+2)%3: its consumers (stage si-1) finished
        // before this stage's top sync — no extra barrier needed.
        issue_stage(tid, si + 2, bufs[(si + 2) % 3], smb); CPCOMMIT();
    }
    __syncthreads();   // K/V visible to all

    // ---------------- attention: mma, TWO heads per warp (h = nh + 2*hid) ----------------
    {
        const int r0 = s16 + q4;
        #pragma unroll
        for (int hid = 0; hid < 2; ++hid){
            const int h = nh + 2 * hid;
            float Sf[32];          // 8 nb x 4
            #pragma unroll
            for (int i = 0; i < 32; ++i) Sf[i] = 0.f;
            // S = Q.K^T  (Q from registers)
            #pragma unroll
            for (int nb = 0; nb < 8; ++nb){
                u32 kaddr = smb + (u32)(OKH + (8 * nb + l8) * 68 + h * 16) * 4 + g8 * 16;
                u32 Bh4[4];
                ldm4(kaddr, Bh4);
                mma16816(&Sf[nb*4], &QAh[hid*8],     &Bh4[0]);
                mma16816(&Sf[nb*4], &QAh[hid*8 + 4], &Bh4[2]);
            }
            // fragment softmax: rows r0 (idx 0,1) and r0+8 (idx 2,3)
            float mx0 = -3.4e38f, mx1 = -3.4e38f;
            #pragma unroll
            for (int nb = 0; nb < 8; ++nb){
                mx0 = fmaxf(mx0, fmaxf(Sf[nb*4],     Sf[nb*4 + 1]));
                mx1 = fmaxf(mx1, fmaxf(Sf[nb*4 + 2], Sf[nb*4 + 3]));
            }
            mx0 = fmaxf(mx0, __shfl_xor_sync(0xffffffffu, mx0, 1));
            mx0 = fmaxf(mx0, __shfl_xor_sync(0xffffffffu, mx0, 2));
            mx1 = fmaxf(mx1, __shfl_xor_sync(0xffffffffu, mx1, 1));
            mx1 = fmaxf(mx1, __shfl_xor_sync(0xffffffffu, mx1, 2));
            float sum0 = 0.f, sum1 = 0.f;
            #pragma unroll
            for (int nb = 0; nb < 8; ++nb){
                Sf[nb*4]     = __expf(Sf[nb*4]     - mx0);
                Sf[nb*4 + 1] = __expf(Sf[nb*4 + 1] - mx0);
                Sf[nb*4 + 2] = __expf(Sf[nb*4 + 2] - mx1);
                Sf[nb*4 + 3] = __expf(Sf[nb*4 + 3] - mx1);
                sum0 += Sf[nb*4] + Sf[nb*4 + 1];
                sum1 += Sf[nb*4 + 2] + Sf[nb*4 + 3];
            }
            sum0 += __shfl_xor_sync(0xffffffffu, sum0, 1);
            sum0 += __shfl_xor_sync(0xffffffffu, sum0, 2);
            sum1 += __shfl_xor_sync(0xffffffffu, sum1, 1);
            sum1 += __shfl_xor_sync(0xffffffffu, sum1, 2);
            float inv0 = 1.0f / sum0, inv1 = 1.0f / sum1;
            // P frags (fp16)
            u32 Pa[16];
            #pragma unroll
            for (int k2 = 0; k2 < 4; ++k2){
                Pa[k2*4]     = hp2(Sf[(2*k2)*4]     * inv0, Sf[(2*k2)*4 + 1] * inv0);
                Pa[k2*4 + 1] = hp2(Sf[(2*k2)*4 + 2] * inv1, Sf[(2*k2)*4 + 3] * inv1);
                Pa[k2*4 + 2] = hp2(Sf[(2*k2+1)*4]     * inv0, Sf[(2*k2+1)*4 + 1] * inv0);
                Pa[k2*4 + 3] = hp2(Sf[(2*k2+1)*4 + 2] * inv1, Sf[(2*k2+1)*4 + 3] * inv1);
            }
            // ctx = P.V
            #pragma unroll
            for (int nb2 = 0; nb2 < 4; ++nb2){
                float C[4] = {0.f,0.f,0.f,0.f};
                u32 vaddr = smb + (u32)(OVTH + (h * 32 + 8 * nb2 + l8) * 36) * 4 + g8 * 16;
                u32 Vh[8];
                ldm4(vaddr,      Vh);
                ldm4(vaddr + 64, Vh + 4);
                #pragma unroll
                for (int k2 = 0; k2 < 4; ++k2)
                    mma16816(C, &Pa[k2*4], &Vh[2*k2]);
                // ctx writeback as fp16 A-layout
                int w = h * 16 + 4 * nb2 + t4;
                smw[OCXH + r0 * 68 + w]       = hp2(C[0], C[1]);
                smw[OCXH + (r0 + 8) * 68 + w] = hp2(C[2], C[3]);
            }
        }
    }
    CPWAIT(0);
    __syncthreads();   // ctx visible; K/V dead -> QA region reusable; W_out bufs ready

    // ---------------- out-proj: ctx(fp16) @ W_out^T + b_out -> QA ----------------
    {
        #pragma unroll
        for (int ks = 0; ks < 8; ++ks){
            u32 aaddr = smb + (u32)(OCXH + (s16 + ((lane >> 3) & 1) * 8 + l8) * 68
                                    + 8 * ks + (lane >> 4) * 4) * 4;
            ldm4(aaddr, &Ah[ks*4]);
        }
        for (int si = 0; si < 2; ++si){
            const u32 bufw = bufs[si];     // stages 6,7 -> bufs 0,1
            for (int j = 0; j < 4; ++j){
                float acc[4] = {0.f, 0.f, 0.f, 0.f};
                u32 baddr = smb + (bufw + (u32)(nh * 32 + 8 * j + l8) * 68) * 4 + g8 * 16;
                #pragma unroll
                for (int p = 0; p < 4; ++p){
                    u32 Bh[4];
                    ldm4(baddr + p * 64, Bh);
                    mma16816(acc, &Ah[8*p],     &Bh[0]);
                    mma16816(acc, &Ah[8*p + 4], &Bh[2]);
                }
                int e0 = si * 64 + nh * 32 + 8 * j + 2 * t4;
                int r0 = s16 + q4;
                sm[OQA + r0 * 128 + e0]           = acc[0] + b_out[e0];
                sm[OQA + r0 * 128 + e0 + 1]       = acc[1] + b_out[e0 + 1];
                sm[OQA + (r0 + 8) * 128 + e0]     = acc[2] + b_out[e0];
                sm[OQA + (r0 + 8) * 128 + e0 + 1] = acc[3] + b_out[e0 + 1];
            }
        }
    }
    __syncthreads();

    // ---------------- pooling + projections ----------------
    #pragma unroll
    for (int i = 0; i < 8; ++i) {
        int l = warp * 8 + i;
        float p = 0.f;
        #pragma unroll
        for (int c = 0; c < 4; ++c) {
            int d = lane + 32 * c;
            p = fmaf(sm[OQA + l * 128 + d], xg[l * 128 + d], p);
        }
        #pragma unroll
        for (int o = 16; o > 0; o >>= 1) p += __shfl_xor_sync(0xffffffffu, p, o);
        if (lane == 0) sm[OAW + l] = p;
    }
    __syncthreads();
    if (warp == 0) {
        float va = sm[OAW + lane], vb = sm[OAW + lane + 32];
        float mx = fmaxf(va, vb);
        #pragma unroll
        for (int o = 16; o > 0; o >>= 1)
            mx = fmaxf(mx, __shfl_xor_sync(0xffffffffu, mx, o));
        float ea = __expf(va - mx), eb = __expf(vb - mx);
        float s = ea + eb;
        #pragma unroll
        for (int o = 16; o > 0; o >>= 1) s += __shfl_xor_sync(0xffffffffu, s, o);
        float inv = 1.0f / s;
        sm[OAW + lane]      = ea * inv;
        sm[OAW + lane + 32] = eb * inv;
    }
    __syncthreads();
    if (tid < 128) {
        int d = tid;
        float wacc = 0.f, s = 0.f, s2 = 0.f, mx = -3.4e38f;
        #pragma unroll 8
        for (int l = 0; l < 64; ++l) {
            float a = sm[OQA + l * 128 + d];
            wacc = fmaf(sm[OAW + l], a, wacc);
            s += a;
            s2 = fmaf(a, a, s2);
            mx = fmaxf(mx, a);
        }
        float mean = s * (1.0f / 64.0f);
        float var  = (s2 - s * mean) * (1.0f / 63.0f);
        sm[OPOOL + d]       = wacc;
        sm[OPOOL + 128 + d] = mx;
        sm[OPOOL + 256 + d] = mean;
        sm[OPOOL + 384 + d] = sqrtf(fmaxf(var, 0.0f));
    }
    __syncthreads();
    {
        int p  = warp >> 1;            // 0..3 pool slot
        int f0 = (warp & 1) * 8;       // 8 outputs per warp
        #pragma unroll
        for (int fi = 0; fi < 8; ++fi) {
            int o = p * 16 + f0 + fi;
            float acc = 0.f;
            #pragma unroll
            for (int c = 0; c < 4; ++c) {
                int d = lane + 32 * c;
                acc = fmaf(sm[OPOOL + p * 128 + d], W_pool[(size_t)o * 128 + d], acc);
            }
            #pragma unroll
            for (int off = 16; off > 0; off >>= 1)
                acc += __shfl_xor_sync(0xffffffffu, acc, off);
            if (lane == 0) out[(size_t)bm * 64 + o] = acc + b_pool[o];
        }
    }
}

extern "C" void kernel_launch(void* const* d_in, const int* in_sizes, int n_in,
                              void* d_out, int out_size)
{
    const float* x      = (const float*)d_in[0];
    const float* W_in   = (const float*)d_in[2];
    const float* b_in   = (const float*)d_in[3];
    const float* W_out  = (const float*)d_in[4];
    const float* b_out  = (const float*)d_in[5];
    const float* W_pool = (const float*)d_in[6];
    const float* b_pool = (const float*)d_in[7];
    float* out = (float*)d_out;

    int nmol = in_sizes[0] / (64 * 128);   // 8192

    prep_kernel<<<256, 256>>>(W_in, W_out);
    cudaFuncSetAttribute(feat_kernel,
                         cudaFuncAttributeMaxDynamicSharedMemorySize, SMEM_BYTES);
    feat_kernel<<<nmol, NT, SMEM_BYTES>>>(x, b_in, b_out,
                                          W_pool, b_pool, out);
}

// round 17
// speedup vs baseline: 1.1123x; 1.0286x over previous
#include <cuda_runtime.h>
#include <cuda_fp16.h>
#include <cstdint>

typedef unsigned long long u64;
typedef unsigned int u32;

// ---------- helpers ----------
__device__ __forceinline__ u32 smem_u32(const void* p){
    u32 a; asm("{ .reg .u64 t; cvta.to.shared.u64 t, %1; cvt.u32.u64 %0, t; }" : "=r"(a) : "l"(p)); return a;
}
// pack f16(lo),f16(hi) -> u32 (lo in low 16 bits)
__device__ __forceinline__ u32 hp2(float lo, float hi){
    u32 r; asm("cvt.rn.f16x2.f32 %0, %1, %2;" : "=r"(r) : "f"(hi), "f"(lo)); return r;
}
__device__ __forceinline__ void mma16816(float* d, const u32* a, const u32* b){
    asm volatile("mma.sync.aligned.m16n8k16.row.col.f32.f16.f16.f32 "
        "{%0,%1,%2,%3}, {%4,%5,%6,%7}, {%8,%9}, {%0,%1,%2,%3};"
        : "+f"(d[0]),"+f"(d[1]),"+f"(d[2]),"+f"(d[3])
        : "r"(a[0]),"r"(a[1]),"r"(a[2]),"r"(a[3]), "r"(b[0]),"r"(b[1]));
}
__device__ __forceinline__ void ldm4(u32 addr, u32* r){
    asm volatile("ldmatrix.sync.aligned.m8n8.x4.shared.b16 {%0,%1,%2,%3}, [%4];"
        : "=r"(r[0]),"=r"(r[1]),"=r"(r[2]),"=r"(r[3]) : "r"(addr));
}
__device__ __forceinline__ void cpa16(u32 dst, const void* src){
    asm volatile("cp.async.cg.shared.global [%0], [%1], 16;" :: "r"(dst), "l"(src));
}
#define CPCOMMIT() asm volatile("cp.async.commit_group;" ::: "memory")
#define CPWAIT(n)  asm volatile("cp.async.wait_group %0;" :: "n"(n) : "memory")

// ---------- prepped weights: [512 rows][136] fp16 (rows 0-383 W_in, 384-511 W_out) ----------
__device__ __align__(16) __half g_w[512 * 136];

__global__ void prep_kernel(const float* __restrict__ W_in, const float* __restrict__ W_out){
    int idx = blockIdx.x * 256 + threadIdx.x;      // 65536
    int r = idx >> 7, c = idx & 127;
    float v = (r < 384) ? W_in[r * 128 + c] : W_out[(r - 384) * 128 + c];
    g_w[r * 136 + c] = __float2half(v);
}

// ---------- smem layout (32-bit word indices) ----------
#define OWS0  0          // 3 W stage buffers, 4352 words each
#define OWS1  4352
#define OWS2  8704
#define OKH   13056      // K fp16 [64 rows][68 words]
#define OVTH  17408      // V^T fp16 [128 d][36 words]
#define OCXH  22016      // ctx fp16 [64 rows][68 words]
#define OQA   13056      // attended fp32 [64][QSTR] — overlaps K+V (dead after attention)
#define QSTR  132        // padded stride: 132*q4 mod 32 = 4*q4 -> conflict-free column writes
#define OPOOL 26368
#define OAW   26880
#define SMEM_FLOATS 26944
#define SMEM_BYTES  (SMEM_FLOATS * 4)   // 107,776 B -> 2 CTAs/SM
#define SCL 0.17677669529663687f        // 1/sqrt(32)

#define NT 256

__device__ __forceinline__ void issue_stage(int tid, int s, u32 bufw, u32 smb){
    const __half* sh = g_w + (size_t)s * 8704;
    for (int i = tid; i < 1088; i += NT){
        cpa16(smb + (bufw + (u32)i * 4) * 4, sh + i * 8);
    }
}

__global__ void __launch_bounds__(NT, 2)
feat_kernel(const float* __restrict__ xg_all,
            const float* __restrict__ b_in, const float* __restrict__ b_out,
            const float* __restrict__ W_pool, const float* __restrict__ b_pool,
            float* __restrict__ out)
{
    extern __shared__ float sm[];
    u32* smw = (u32*)sm;
    const u32 smb = smem_u32(sm);
    const int tid  = threadIdx.x;
    const int lane = tid & 31;
    const int warp = tid >> 5;        // 0..7
    const int q4   = lane >> 2;       // 0..7
    const int t4   = lane & 3;        // 0..3
    const int s16  = (warp & 3) * 16; // row stripe
    const int nh   = warp >> 2;       // 0..1 column half
    const int l8   = lane & 7;        // ldmatrix row-lane
    const int g8   = lane >> 3;       // ldmatrix matrix-group
    const int bm   = blockIdx.x;
    const float* xg = xg_all + (size_t)bm * (64 * 128);
    const u32 bufs[3] = {OWS0, OWS1, OWS2};

    // prefetch W stages 0,1
    issue_stage(tid, 0, OWS0, smb); CPCOMMIT();
    issue_stage(tid, 1, OWS1, smb); CPCOMMIT();

    // ---- A fragments from gmem x (fp16) ----
    u32 Ah[32];
    #pragma unroll
    for (int ks = 0; ks < 8; ++ks){
        #pragma unroll
        for (int qq = 0; qq < 4; ++qq){
            int rr = s16 + q4 + (qq & 1) * 8;
            int k  = ks * 16 + 2 * t4 + (qq >> 1) * 8;
            float2 v = *(const float2*)(xg + rr * 128 + k);
            Ah[4 * ks + qq] = hp2(v.x, v.y);
        }
    }

    u32 QAh[16];   // Q A-frags: 2 heads x 2 ksteps x 4 (register-resident)

    // ---------------- QKV, triple-buffered, ONE sync per stage, issue at BOTTOM ----------------
    for (int si = 0; si < 6; ++si){
        CPWAIT(1);
        __syncthreads();                             // stage si data visible
        const u32 bufw = bufs[si % 3];
        for (int j = 0; j < 4; ++j){
            float acc[4] = {0.f, 0.f, 0.f, 0.f};
            u32 baddr = smb + (bufw + (u32)(nh * 32 + 8 * j + l8) * 68) * 4 + g8 * 16;
            #pragma unroll
            for (int p = 0; p < 4; ++p){
                u32 Bh[4];
                ldm4(baddr + p * 64, Bh);
                mma16816(acc, &Ah[8*p],     &Bh[0]);
                mma16816(acc, &Ah[8*p + 4], &Bh[2]);
            }
            int e0 = si * 64 + nh * 32 + 8 * j + 2 * t4;
            int r0 = s16 + q4;
            float v0 = acc[0] + b_in[e0];
            float v1 = acc[1] + b_in[e0 + 1];
            float v2 = acc[2] + b_in[e0];
            float v3 = acc[3] + b_in[e0 + 1];
            if (si < 2){
                // Q (scaled) -> register A-frags (R9-validated mapping)
                v0 *= SCL; v1 *= SCL; v2 *= SCL; v3 *= SCL;
                int base = si * 8 + (j >> 1) * 4 + (j & 1) * 2;
                QAh[base]     = hp2(v0, v1);
                QAh[base + 1] = hp2(v2, v3);
            } else if (si < 4){
                // K row-major fp16
                int kw = (si - 2) * 32 + nh * 16 + 4 * j + t4;
                smw[OKH + r0 * 68 + kw]       = hp2(v0, v1);
                smw[OKH + (r0 + 8) * 68 + kw] = hp2(v2, v3);
            } else {
                // V^T fp16 (halfword stores)
                int d0 = (si - 4) * 64 + nh * 32 + 8 * j + 2 * t4;
                __half* vth = (__half*)&smw[OVTH];
                vth[d0 * 72 + r0]           = __float2half(v0);
                vth[(d0 + 1) * 72 + r0]     = __float2half(v1);
                vth[d0 * 72 + r0 + 8]       = __float2half(v2);
                vth[(d0 + 1) * 72 + r0 + 8] = __float2half(v3);
            }
        }
        // issue stage si+2 into buf (si+2)%3: its consumers (stage si-1) finished
        // before this stage's top sync — no extra barrier needed.
        issue_stage(tid, si + 2, bufs[(si + 2) % 3], smb); CPCOMMIT();
    }
    __syncthreads();   // K/V visible to all

    // ---------------- attention: mma, TWO heads per warp (h = nh + 2*hid) ----------------
    {
        const int r0 = s16 + q4;
        #pragma unroll
        for (int hid = 0; hid < 2; ++hid){
            const int h = nh + 2 * hid;
            float Sf[32];          // 8 nb x 4
            #pragma unroll
            for (int i = 0; i < 32; ++i) Sf[i] = 0.f;
            // S = Q.K^T  (Q from registers)
            #pragma unroll
            for (int nb = 0; nb < 8; ++nb){
                u32 kaddr = smb + (u32)(OKH + (8 * nb + l8) * 68 + h * 16) * 4 + g8 * 16;
                u32 Bh4[4];
                ldm4(kaddr, Bh4);
                mma16816(&Sf[nb*4], &QAh[hid*8],     &Bh4[0]);
                mma16816(&Sf[nb*4], &QAh[hid*8 + 4], &Bh4[2]);
            }
            // fragment softmax: rows r0 (idx 0,1) and r0+8 (idx 2,3)
            float mx0 = -3.4e38f, mx1 = -3.4e38f;
            #pragma unroll
            for (int nb = 0; nb < 8; ++nb){
                mx0 = fmaxf(mx0, fmaxf(Sf[nb*4],     Sf[nb*4 + 1]));
                mx1 = fmaxf(mx1, fmaxf(Sf[nb*4 + 2], Sf[nb*4 + 3]));
            }
            mx0 = fmaxf(mx0, __shfl_xor_sync(0xffffffffu, mx0, 1));
            mx0 = fmaxf(mx0, __shfl_xor_sync(0xffffffffu, mx0, 2));
            mx1 = fmaxf(mx1, __shfl_xor_sync(0xffffffffu, mx1, 1));
            mx1 = fmaxf(mx1, __shfl_xor_sync(0xffffffffu, mx1, 2));
            float sum0 = 0.f, sum1 = 0.f;
            #pragma unroll
            for (int nb = 0; nb < 8; ++nb){
                Sf[nb*4]     = __expf(Sf[nb*4]     - mx0);
                Sf[nb*4 + 1] = __expf(Sf[nb*4 + 1] - mx0);
                Sf[nb*4 + 2] = __expf(Sf[nb*4 + 2] - mx1);
                Sf[nb*4 + 3] = __expf(Sf[nb*4 + 3] - mx1);
                sum0 += Sf[nb*4] + Sf[nb*4 + 1];
                sum1 += Sf[nb*4 + 2] + Sf[nb*4 + 3];
            }
            sum0 += __shfl_xor_sync(0xffffffffu, sum0, 1);
            sum0 += __shfl_xor_sync(0xffffffffu, sum0, 2);
            sum1 += __shfl_xor_sync(0xffffffffu, sum1, 1);
            sum1 += __shfl_xor_sync(0xffffffffu, sum1, 2);
            float inv0 = 1.0f / sum0, inv1 = 1.0f / sum1;
            // P frags (fp16)
            u32 Pa[16];
            #pragma unroll
            for (int k2 = 0; k2 < 4; ++k2){
                Pa[k2*4]     = hp2(Sf[(2*k2)*4]     * inv0, Sf[(2*k2)*4 + 1] * inv0);
                Pa[k2*4 + 1] = hp2(Sf[(2*k2)*4 + 2] * inv1, Sf[(2*k2)*4 + 3] * inv1);
                Pa[k2*4 + 2] = hp2(Sf[(2*k2+1)*4]     * inv0, Sf[(2*k2+1)*4 + 1] * inv0);
                Pa[k2*4 + 3] = hp2(Sf[(2*k2+1)*4 + 2] * inv1, Sf[(2*k2+1)*4 + 3] * inv1);
            }
            // ctx = P.V
            #pragma unroll
            for (int nb2 = 0; nb2 < 4; ++nb2){
                float C[4] = {0.f,0.f,0.f,0.f};
                u32 vaddr = smb + (u32)(OVTH + (h * 32 + 8 * nb2 + l8) * 36) * 4 + g8 * 16;
                u32 Vh[8];
                ldm4(vaddr,      Vh);
                ldm4(vaddr + 64, Vh + 4);
                #pragma unroll
                for (int k2 = 0; k2 < 4; ++k2)
                    mma16816(C, &Pa[k2*4], &Vh[2*k2]);
                // ctx writeback as fp16 A-layout
                int w = h * 16 + 4 * nb2 + t4;
                smw[OCXH + r0 * 68 + w]       = hp2(C[0], C[1]);
                smw[OCXH + (r0 + 8) * 68 + w] = hp2(C[2], C[3]);
            }
        }
    }
    CPWAIT(0);
    __syncthreads();   // ctx visible; K/V dead -> QA region reusable; W_out bufs ready

    // ---------------- out-proj: ctx(fp16) @ W_out^T + b_out -> QA ----------------
    {
        #pragma unroll
        for (int ks = 0; ks < 8; ++ks){
            u32 aaddr = smb + (u32)(OCXH + (s16 + ((lane >> 3) & 1) * 8 + l8) * 68
                                    + 8 * ks + (lane >> 4) * 4) * 4;
            ldm4(aaddr, &Ah[ks*4]);
        }
        for (int si = 0; si < 2; ++si){
            const u32 bufw = bufs[si];     // stages 6,7 -> bufs 0,1
            for (int j = 0; j < 4; ++j){
                float acc[4] = {0.f, 0.f, 0.f, 0.f};
                u32 baddr = smb + (bufw + (u32)(nh * 32 + 8 * j + l8) * 68) * 4 + g8 * 16;
                #pragma unroll
                for (int p = 0; p < 4; ++p){
                    u32 Bh[4];
                    ldm4(baddr + p * 64, Bh);
                    mma16816(acc, &Ah[8*p],     &Bh[0]);
                    mma16816(acc, &Ah[8*p + 4], &Bh[2]);
                }
                int e0 = si * 64 + nh * 32 + 8 * j + 2 * t4;
                int r0 = s16 + q4;
                sm[OQA + r0 * QSTR + e0]           = acc[0] + b_out[e0];
                sm[OQA + r0 * QSTR + e0 + 1]       = acc[1] + b_out[e0 + 1];
                sm[OQA + (r0 + 8) * QSTR + e0]     = acc[2] + b_out[e0];
                sm[OQA + (r0 + 8) * QSTR + e0 + 1] = acc[3] + b_out[e0 + 1];
            }
        }
    }
    __syncthreads();

    // ---------------- pooling + projections ----------------
    #pragma unroll
    for (int i = 0; i < 8; ++i) {
        int l = warp * 8 + i;
        float p = 0.f;
        #pragma unroll
        for (int c = 0; c < 4; ++c) {
            int d = lane + 32 * c;
            p = fmaf(sm[OQA + l * QSTR + d], xg[l * 128 + d], p);
        }
        #pragma unroll
        for (int o = 16; o > 0; o >>= 1) p += __shfl_xor_sync(0xffffffffu, p, o);
        if (lane == 0) sm[OAW + l] = p;
    }
    __syncthreads();
    if (warp == 0) {
        float va = sm[OAW + lane], vb = sm[OAW + lane + 32];
        float mx = fmaxf(va, vb);
        #pragma unroll
        for (int o = 16; o > 0; o >>= 1)
            mx = fmaxf(mx, __shfl_xor_sync(0xffffffffu, mx, o));
        float ea = __expf(va - mx), eb = __expf(vb - mx);
        float s = ea + eb;
        #pragma unroll
        for (int o = 16; o > 0; o >>= 1) s += __shfl_xor_sync(0xffffffffu, s, o);
        float inv = 1.0f / s;
        sm[OAW + lane]      = ea * inv;
        sm[OAW + lane + 32] = eb * inv;
    }
    __syncthreads();
    if (tid < 128) {
        int d = tid;
        float wacc = 0.f, s = 0.f, s2 = 0.f, mx = -3.4e38f;
        #pragma unroll 8
        for (int l = 0; l < 64; ++l) {
            float a = sm[OQA + l * QSTR + d];
            wacc = fmaf(sm[OAW + l], a, wacc);
            s += a;
            s2 = fmaf(a, a, s2);
            mx = fmaxf(mx, a);
        }
        float mean = s * (1.0f / 64.0f);
        float var  = (s2 - s * mean) * (1.0f / 63.0f);
        sm[OPOOL + d]       = wacc;
        sm[OPOOL + 128 + d] = mx;
        sm[OPOOL + 256 + d] = mean;
        sm[OPOOL + 384 + d] = sqrtf(fmaxf(var, 0.0f));
    }
    __syncthreads();
    {
        int p  = warp >> 1;            // 0..3 pool slot
        int f0 = (warp & 1) * 8;       // 8 outputs per warp
        #pragma unroll
        for (int fi = 0; fi < 8; ++fi) {
            int o = p * 16 + f0 + fi;
            float acc = 0.f;
            #pragma unroll
            for (int c = 0; c < 4; ++c) {
                int d = lane + 32 * c;
                acc = fmaf(sm[OPOOL + p * 128 + d], W_pool[(size_t)o * 128 + d], acc);
            }
            #pragma unroll
            for (int off = 16; off > 0; off >>= 1)
                acc += __shfl_xor_sync(0xffffffffu, acc, off);
            if (lane == 0) out[(size_t)bm * 64 + o] = acc + b_pool[o];
        }
    }
}

extern "C" void kernel_launch(void* const* d_in, const int* in_sizes, int n_in,
                              void* d_out, int out_size)
{
    const float* x      = (const float*)d_in[0];
    const float* W_in   = (const float*)d_in[2];
    const float* b_in   = (const float*)d_in[3];
    const float* W_out  = (const float*)d_in[4];
    const float* b_out  = (const float*)d_in[5];
    const float* W_pool = (const float*)d_in[6];
    const float* b_pool = (const float*)d_in[7];
    float* out = (float*)d_out;

    int nmol = in_sizes[0] / (64 * 128);   // 8192

    prep_kernel<<<256, 256>>>(W_in, W_out);
    cudaFuncSetAttribute(feat_kernel,
                         cudaFuncAttributeMaxDynamicSharedMemorySize, SMEM_BYTES);
    feat_kernel<<<nmol, NT, SMEM_BYTES>>>(x, b_in, b_out,
                                          W_pool, b_pool, out);
}